// round 14
// baseline (speedup 1.0000x reference)
#include <cuda_runtime.h>
#include <cstdint>

// Problem constants
#define Bc 4
#define Tc 2048
#define Cc 1024
#define Hc 16
#define Dc 64
#define BHTD ((size_t)Bc * Hc * Tc * Dc)   // 8388608

// Scratch (static device globals — no allocation allowed)
// g_qkv: Q,K segments [b][h][T][D]; V segment stored TRANSPOSED [b][h][D][T]
__device__ float g_qkv[3 * Bc * Hc * Tc * Dc];
__device__ float g_att[(size_t)Bc * Tc * Cc];          // [B,T,C] (tf32-rounded)
__device__ float g_xr[(size_t)Bc * Tc * Cc];           // x, tf32-rounded
__device__ float g_wqkvT[3 * Cc * Cc];                 // Wqkv^T [3072,1024], tf32-rounded
__device__ float g_woutT[(size_t)Cc * Cc];             // Wout^T [1024,1024], tf32-rounded

__device__ __forceinline__ float neg_inf() { return __int_as_float(0xff800000); }

__device__ __forceinline__ float tf32r(float x) {
    float y;
    asm("cvt.rna.tf32.f32 %0, %1;" : "=f"(y) : "f"(x));
    return y;
}

__device__ __forceinline__ uint32_t smem_u32(const void* p) {
    uint32_t a;
    asm("{ .reg .u64 t; cvta.to.shared.u64 t, %1; cvt.u32.u64 %0, t; }"
        : "=r"(a) : "l"(p));
    return a;
}

__device__ __forceinline__ void cp_async16(uint32_t smem_dst, const void* gsrc) {
    asm volatile("cp.async.cg.shared.global [%0], [%1], 16;"
                 :: "r"(smem_dst), "l"(gsrc) : "memory");
}
__device__ __forceinline__ void cp_async_commit() {
    asm volatile("cp.async.commit_group;" ::: "memory");
}
__device__ __forceinline__ void cp_async_wait1() {
    asm volatile("cp.async.wait_group 1;" ::: "memory");
}
__device__ __forceinline__ void cp_async_wait0() {
    asm volatile("cp.async.wait_group 0;" ::: "memory");
}

// mma.sync m16n8k8 tf32 (A row-major, B col-major, fp32 accum)
__device__ __forceinline__ void mma_tf32(float* d, const uint32_t* a, const uint32_t* b) {
    asm volatile(
        "mma.sync.aligned.m16n8k8.row.col.f32.tf32.tf32.f32 "
        "{%0,%1,%2,%3}, {%4,%5,%6,%7}, {%8,%9}, {%0,%1,%2,%3};"
        : "+f"(d[0]), "+f"(d[1]), "+f"(d[2]), "+f"(d[3])
        : "r"(a[0]), "r"(a[1]), "r"(a[2]), "r"(a[3]), "r"(b[0]), "r"(b[1]));
}

// ldmatrix x4: four 8-row x 16-byte matrices (== four 8x4 tf32 tiles)
__device__ __forceinline__ void ldsm4(uint32_t* r, uint32_t addr) {
    asm volatile("ldmatrix.sync.aligned.m8n8.x4.shared.b16 {%0,%1,%2,%3}, [%4];"
        : "=r"(r[0]), "=r"(r[1]), "=r"(r[2]), "=r"(r[3]) : "r"(addr));
}

// ---------------------------------------------------------------------------
// Elementwise tf32 rounding
// ---------------------------------------------------------------------------
__global__ __launch_bounds__(256)
void round_kernel(const float* __restrict__ in, float* __restrict__ out, int n)
{
    const int i = (blockIdx.x * 256 + threadIdx.x) * 4;
    if (i < n) {
        float4 v = *(const float4*)(in + i);
        v.x = tf32r(v.x); v.y = tf32r(v.y); v.z = tf32r(v.z); v.w = tf32r(v.w);
        *(float4*)(out + i) = v;
    }
}

// ---------------------------------------------------------------------------
// Transpose + tf32 round: out[c][r] = rna_tf32(in[r][c])  (R rows, C cols)
// ---------------------------------------------------------------------------
__global__ __launch_bounds__(256)
void transpose_kernel(const float* __restrict__ in, float* __restrict__ out,
                      int R, int C)
{
    __shared__ float tile[32][33];
    const int c0 = blockIdx.x * 32;
    const int r0 = blockIdx.y * 32;
    const int x = threadIdx.x & 31;
    const int y = threadIdx.x >> 5;
#pragma unroll
    for (int i = 0; i < 32; i += 8)
        tile[y + i][x] = in[(size_t)(r0 + y + i) * C + c0 + x];
    __syncthreads();
#pragma unroll
    for (int i = 0; i < 32; i += 8)
        out[(size_t)(c0 + y + i) * R + r0 + x] = tf32r(tile[x][y + i]);
}

// ---------------------------------------------------------------------------
// tf32 mma.sync GEMM:  C[M,N] = A[M,K] @ Bt[N,K]^T + bias
// CTA 128x128, 128 threads = 4 warps (2m x 2n), warp tile 64x64, BK=32,
// 3-stage cp.async pipeline, ldmatrix.x4 fragment loads with DOUBLE-BUFFERED
// fragments (phase p+1 frags load during phase p MMAs), warp-staggered ks.
// MODE 0: plain write.  MODE 1: scatter into g_qkv (tf32-rounded;
//         V segment written TRANSPOSED as [b][h][D][T]).
// ---------------------------------------------------------------------------
#define PAD32 36                                 // 32 data + 4 pad floats
#define GSTG32 (128 * PAD32)                     // floats per operand per stage
#define GEMM_SMEM (2 * 3 * GSTG32 * 4)           // 110592 bytes

#define LDFRAGS(AU, BU, KS, BSEL) do {                                        \
    _Pragma("unroll")                                                         \
    for (int i_ = 0; i_ < 4; i_++)                                            \
        ldsm4(afb[BSEL][i_], (AU) + 4u * (i_ * 16 * PAD32 + (KS) * 8));       \
    _Pragma("unroll")                                                         \
    for (int jp_ = 0; jp_ < 4; jp_++) {                                       \
        uint32_t r_[4];                                                       \
        ldsm4(r_, (BU) + 4u * (jp_ * 16 * PAD32 + (KS) * 8));                 \
        bfb[BSEL][2 * jp_][0]     = r_[0];                                    \
        bfb[BSEL][2 * jp_][1]     = r_[1];                                    \
        bfb[BSEL][2 * jp_ + 1][0] = r_[2];                                    \
        bfb[BSEL][2 * jp_ + 1][1] = r_[3];                                    \
    }                                                                         \
} while (0)

template <int MODE>
__global__ __launch_bounds__(128, 2)
void gemm_mma(const float* __restrict__ A, const float* __restrict__ Bt,
              const float* __restrict__ bias, float* __restrict__ Cout,
              int M, int N, int K)
{
    extern __shared__ float sm[];
    float* As = sm;                  // [3][GSTG32]
    float* Bs = sm + 3 * GSTG32;     // [3][GSTG32]

    const int tid = threadIdx.x;
    const int wid = tid >> 5;            // 0..3
    const int lid = tid & 31;
    const int g   = lid >> 2;
    const int tg  = lid & 3;
    const int wm  = (wid >> 1) * 64;
    const int wn  = (wid & 1) * 64;

    const int m0 = blockIdx.y * 128;
    const int n0 = blockIdx.x * 128;
    const int KT = K >> 5;               // BK=32 tiles

    // ldmatrix per-lane row/col (in floats) within a ks-block
    const int a_r = ((lid >> 3) & 1) * 8 + (lid & 7);
    const int a_c = (lid >> 4) * 4;
    const int b_r = (lid >> 4) * 8 + (lid & 7);
    const int b_c = ((lid >> 3) & 1) * 4;

    float acc[4][8][4];
#pragma unroll
    for (int i = 0; i < 4; i++)
#pragma unroll
        for (int j = 0; j < 8; j++)
#pragma unroll
            for (int r = 0; r < 4; r++) acc[i][j][r] = 0.0f;

    // loader: 1024 16B chunks per operand, 8 per thread per operand
    auto load_stage = [&](int kt, int stg) {
        const float* ga = A  + (size_t)m0 * K + kt * 32;
        const float* gb = Bt + (size_t)n0 * K + kt * 32;
        const uint32_t sa = smem_u32(As + stg * GSTG32);
        const uint32_t sb = smem_u32(Bs + stg * GSTG32);
#pragma unroll
        for (int i = 0; i < 8; i++) {
            const int c = tid + i * 128;          // 0..1023
            const int row = c >> 3;               // 0..127
            const int c16 = c & 7;                // 16B chunk in row
            cp_async16(sa + (row * PAD32 + c16 * 4) * 4, ga + (size_t)row * K + c16 * 4);
            cp_async16(sb + (row * PAD32 + c16 * 4) * 4, gb + (size_t)row * K + c16 * 4);
        }
        cp_async_commit();
    };

    load_stage(0, 0);
    load_stage(1, 1);

    uint32_t afb[2][4][4], bfb[2][8][2];
    const uint32_t aoff = 4u * ((wm + a_r) * PAD32 + a_c);
    const uint32_t boff = 4u * ((wn + b_r) * PAD32 + b_c);

    int cur = 0;
    for (int kt = 0; kt < KT; kt++) {
        if (kt + 1 < KT) cp_async_wait1();   // tile kt resident
        else             cp_async_wait0();   // last tile: everything done
        __syncthreads();
        const int nxt = (cur + 2 >= 3) ? cur - 1 : cur + 2;
        if (kt + 2 < KT) load_stage(kt + 2, nxt);

        const uint32_t au = smem_u32(As + cur * GSTG32) + aoff;
        const uint32_t bu = smem_u32(Bs + cur * GSTG32) + boff;

        LDFRAGS(au, bu, (wid & 3), 0);       // phase-0 frags
#pragma unroll
        for (int p = 0; p < 4; p++) {
            const int pb = p & 1;
            if (p < 3) LDFRAGS(au, bu, ((p + 1 + wid) & 3), ((p + 1) & 1));
#pragma unroll
            for (int i = 0; i < 4; i++)
#pragma unroll
                for (int j = 0; j < 8; j++)
                    mma_tf32(acc[i][j], afb[pb][i], bfb[pb][j]);
        }
        cur = (cur + 1 >= 3) ? 0 : cur + 1;
    }

    // epilogue
#pragma unroll
    for (int i = 0; i < 4; i++) {
        const int r0 = m0 + wm + i * 16 + g;
        const int r1 = r0 + 8;
#pragma unroll
        for (int j = 0; j < 8; j++) {
            const int c = n0 + wn + j * 8 + 2 * tg;
            const float2 bv = *(const float2*)(bias + c);
            float2 v0, v1;
            v0.x = acc[i][j][0] + bv.x;  v0.y = acc[i][j][1] + bv.y;
            v1.x = acc[i][j][2] + bv.x;  v1.y = acc[i][j][3] + bv.y;
            if (MODE == 0) {
                *(float2*)(Cout + (size_t)r0 * N + c) = v0;
                *(float2*)(Cout + (size_t)r1 * N + c) = v1;
            } else {
                // qkv feeds tf32 attention mmas -> round at the source
                v0.x = tf32r(v0.x); v0.y = tf32r(v0.y);
                v1.x = tf32r(v1.x); v1.y = tf32r(v1.y);
                const int sidx = c >> 10;
                const int rem  = c & (Cc - 1);
                const int h    = rem >> 6;
                const int dd   = rem & (Dc - 1);
                const int b0i = r0 >> 11, t0i = r0 & (Tc - 1);
                const int b1i = r1 >> 11, t1i = r1 & (Tc - 1);
                const size_t bh0 = (size_t)(sidx * Bc + b0i) * Hc + h;
                const size_t bh1 = (size_t)(sidx * Bc + b1i) * Hc + h;
                if (sidx < 2) {
                    *(float2*)&g_qkv[(bh0 * Tc + t0i) * 64 + dd] = v0;
                    *(float2*)&g_qkv[(bh1 * Tc + t1i) * 64 + dd] = v1;
                } else {
                    // V transposed: [bh][d][t]
                    float* p0 = &g_qkv[bh0 * ((size_t)64 * Tc) + (size_t)dd * Tc + t0i];
                    float* p1 = &g_qkv[bh1 * ((size_t)64 * Tc) + (size_t)dd * Tc + t1i];
                    p0[0]  = v0.x;  p0[Tc] = v0.y;
                    p1[0]  = v1.x;  p1[Tc] = v1.y;
                }
            }
        }
    }
}

// ---------------------------------------------------------------------------
// Tensor-core causal flash attention (tf32 mma.sync), ldmatrix everywhere.
// (unchanged from round 13)
// ---------------------------------------------------------------------------
#define KS_ST 68
#define PS_ST 68
#define ATT_SMEM ((64 * KS_ST + 64 * KS_ST + 4 * 16 * PS_ST) * 4)   // 52224 B

__global__ __launch_bounds__(128)
void attn_mma_kernel(const float* __restrict__ Q, const float* __restrict__ K,
                     const float* __restrict__ VT, float* __restrict__ O)
{
    extern __shared__ float sm[];
    float* Ks = sm;                       // [64][68]  (rows = keys)
    float* Vs = sm + 64 * KS_ST;          // [64][68]  (rows = d)
    float* Ps = Vs + 64 * KS_ST;          // [4][16][68]

    const int tid = threadIdx.x;
    const int wid = tid >> 5;
    const int lid = tid & 31;
    const int g   = lid >> 2;
    const int tg  = lid & 3;
    const int bh  = blockIdx.y;
    const int b   = bh >> 4;
    const int h   = bh & 15;
    const int qb  = gridDim.x - 1 - blockIdx.x;   // heavy blocks first
    const int q0  = qb * 64;

    // ldmatrix per-lane row/col (floats)
    const int a_r = ((lid >> 3) & 1) * 8 + (lid & 7);
    const int a_c = (lid >> 4) * 4;
    const int b_r = (lid >> 4) * 8 + (lid & 7);
    const int b_c = ((lid >> 3) & 1) * 4;

    const float SCALE = 0.125f * 1.44269504088896340736f;

    const float* qbase = Q + ((size_t)bh * Tc + q0 + wid * 16) * Dc;
    uint32_t qf[8][4];
#pragma unroll
    for (int k = 0; k < 8; k++) {
        qf[k][0] = __float_as_uint(tf32r(qbase[(size_t)g * Dc       + 8 * k + tg]     * SCALE));
        qf[k][1] = __float_as_uint(tf32r(qbase[(size_t)(g + 8) * Dc + 8 * k + tg]     * SCALE));
        qf[k][2] = __float_as_uint(tf32r(qbase[(size_t)g * Dc       + 8 * k + tg + 4] * SCALE));
        qf[k][3] = __float_as_uint(tf32r(qbase[(size_t)(g + 8) * Dc + 8 * k + tg + 4] * SCALE));
    }

    float o[8][4];
#pragma unroll
    for (int nt = 0; nt < 8; nt++)
#pragma unroll
        for (int r = 0; r < 4; r++) o[nt][r] = 0.0f;
    float m0 = neg_inf(), m1 = neg_inf(), l0 = 0.0f, l1 = 0.0f;

    const float* kg  = K  + (size_t)bh * Tc * Dc;           // [t][d]
    const float* vtg = VT + (size_t)bh * Dc * Tc;           // [d][t]
    const uint32_t ksu = smem_u32(Ks);
    const uint32_t vsu = smem_u32(Vs);
    float* Pw = Ps + wid * 16 * PS_ST;

    const uint32_t ku = ksu + 4u * (b_r * KS_ST + b_c);
    const uint32_t vu = vsu + 4u * (b_r * KS_ST + b_c);
    const uint32_t pu = smem_u32(Pw) + 4u * (a_r * PS_ST + a_c);

    auto load_k = [&](int t0) {
#pragma unroll
        for (int i = 0; i < 8; i++) {
            const int c = tid + i * 128;
            const int row = c >> 4;              // key index
            const int c16 = c & 15;
            cp_async16(ksu + (row * KS_ST + c16 * 4) * 4,
                       kg + (size_t)(t0 + row) * Dc + c16 * 4);
        }
        cp_async_commit();
    };
    auto load_v = [&](int t0) {
#pragma unroll
        for (int i = 0; i < 8; i++) {
            const int c = tid + i * 128;
            const int row = c >> 4;              // d index
            const int c16 = c & 15;
            cp_async16(vsu + (row * KS_ST + c16 * 4) * 4,
                       vtg + (size_t)row * Tc + t0 + c16 * 4);
        }
        cp_async_commit();
    };

    const int NT = qb + 1;
    load_k(0);
    load_v(0);

    for (int it = 0; it < NT; it++) {
        const int t0 = it * 64;

        cp_async_wait1();            // K_it resident (V_it is the newer group)
        __syncthreads();

        // S = Q K^T   (16 x 64 per warp), K-frags via ldmatrix
        float s[8][4];
#pragma unroll
        for (int nt = 0; nt < 8; nt++)
            s[nt][0] = s[nt][1] = s[nt][2] = s[nt][3] = 0.0f;
#pragma unroll
        for (int ks = 0; ks < 8; ks++) {
            uint32_t bf[8][2];
#pragma unroll
            for (int jp = 0; jp < 4; jp++) {
                uint32_t r[4];
                ldsm4(r, ku + 4u * (jp * 16 * KS_ST + ks * 8));
                bf[2 * jp][0]     = r[0];
                bf[2 * jp][1]     = r[1];
                bf[2 * jp + 1][0] = r[2];
                bf[2 * jp + 1][1] = r[3];
            }
#pragma unroll
            for (int nt = 0; nt < 8; nt++)
                mma_tf32(s[nt], qf[ks], bf[nt]);
        }

        __syncthreads();             // all warps done reading Ks
        if (it + 1 < NT) load_k(t0 + 64);   // overlaps softmax + PV below

        if (t0 == q0) {              // causal mask on diagonal block
            const int r0 = wid * 16 + g;
            const int r1 = r0 + 8;
#pragma unroll
            for (int nt = 0; nt < 8; nt++) {
                const int c0i = nt * 8 + 2 * tg;
                if (c0i     > r0) s[nt][0] = neg_inf();
                if (c0i + 1 > r0) s[nt][1] = neg_inf();
                if (c0i     > r1) s[nt][2] = neg_inf();
                if (c0i + 1 > r1) s[nt][3] = neg_inf();
            }
        }

        float mt0 = m0, mt1 = m1;
#pragma unroll
        for (int nt = 0; nt < 8; nt++) {
            mt0 = fmaxf(mt0, fmaxf(s[nt][0], s[nt][1]));
            mt1 = fmaxf(mt1, fmaxf(s[nt][2], s[nt][3]));
        }
        mt0 = fmaxf(mt0, __shfl_xor_sync(0xffffffffu, mt0, 1));
        mt0 = fmaxf(mt0, __shfl_xor_sync(0xffffffffu, mt0, 2));
        mt1 = fmaxf(mt1, __shfl_xor_sync(0xffffffffu, mt1, 1));
        mt1 = fmaxf(mt1, __shfl_xor_sync(0xffffffffu, mt1, 2));

        const float a0 = exp2f(m0 - mt0);
        const float a1 = exp2f(m1 - mt1);
        m0 = mt0; m1 = mt1;
        l0 *= a0;  l1 *= a1;
#pragma unroll
        for (int nt = 0; nt < 8; nt++) {
            o[nt][0] *= a0; o[nt][1] *= a0;
            o[nt][2] *= a1; o[nt][3] *= a1;
        }

#pragma unroll
        for (int nt = 0; nt < 8; nt++) {
            float p00 = exp2f(s[nt][0] - mt0);
            float p01 = exp2f(s[nt][1] - mt0);
            float p10 = exp2f(s[nt][2] - mt1);
            float p11 = exp2f(s[nt][3] - mt1);
            p00 = tf32r(p00); p01 = tf32r(p01);
            p10 = tf32r(p10); p11 = tf32r(p11);
            l0 += p00 + p01;
            l1 += p10 + p11;
            *(float2*)&Pw[g * PS_ST + nt * 8 + 2 * tg]       = make_float2(p00, p01);
            *(float2*)&Pw[(g + 8) * PS_ST + nt * 8 + 2 * tg] = make_float2(p10, p11);
        }
        __syncwarp();

        if (it + 1 < NT) cp_async_wait1();   // V_it resident (K_{it+1} in flight)
        else             cp_async_wait0();   // final V: guarantee completion
        __syncthreads();

        // O += P V : P-frags and V-frags via ldmatrix
#pragma unroll
        for (int ks = 0; ks < 8; ks++) {
            uint32_t af[4];
            ldsm4(af, pu + 4u * (ks * 8));
            uint32_t bf[8][2];
#pragma unroll
            for (int jp = 0; jp < 4; jp++) {
                uint32_t r[4];
                ldsm4(r, vu + 4u * (jp * 16 * KS_ST + ks * 8));
                bf[2 * jp][0]     = r[0];
                bf[2 * jp][1]     = r[1];
                bf[2 * jp + 1][0] = r[2];
                bf[2 * jp + 1][1] = r[3];
            }
#pragma unroll
            for (int nt = 0; nt < 8; nt++)
                mma_tf32(o[nt], af, bf[nt]);
        }

        __syncthreads();             // all warps done reading Vs
        if (it + 1 < NT) load_v(t0 + 64);   // overlaps next S
    }

    l0 += __shfl_xor_sync(0xffffffffu, l0, 1);
    l0 += __shfl_xor_sync(0xffffffffu, l0, 2);
    l1 += __shfl_xor_sync(0xffffffffu, l1, 1);
    l1 += __shfl_xor_sync(0xffffffffu, l1, 2);
    const float inv0 = 1.0f / l0;
    const float inv1 = 1.0f / l1;

    const int row0 = q0 + wid * 16 + g;
    const int row1 = row0 + 8;
    float* ob0 = O + ((size_t)b * Tc + row0) * Cc + h * Dc;
    float* ob1 = O + ((size_t)b * Tc + row1) * Cc + h * Dc;
#pragma unroll
    for (int nt = 0; nt < 8; nt++) {
        const int c = nt * 8 + 2 * tg;
        *(float2*)(ob0 + c) = make_float2(tf32r(o[nt][0] * inv0), tf32r(o[nt][1] * inv0));
        *(float2*)(ob1 + c) = make_float2(tf32r(o[nt][2] * inv1), tf32r(o[nt][3] * inv1));
    }
}

// ---------------------------------------------------------------------------
// Host launcher
// ---------------------------------------------------------------------------
extern "C" void kernel_launch(void* const* d_in, const int* in_sizes, int n_in,
                              void* d_out, int out_size)
{
    const float* x    = (const float*)d_in[0];
    // d_in[1] = mask (static causal — unused)
    const float* Wqkv = (const float*)d_in[2];
    const float* bqkv = (const float*)d_in[3];
    const float* Wout = (const float*)d_in[4];
    const float* bout = (const float*)d_in[5];
    float* out = (float*)d_out;

    float* qkv = nullptr;
    float* att = nullptr;
    float* xr = nullptr;
    float* wqkvT = nullptr;
    float* woutT = nullptr;
    cudaGetSymbolAddress((void**)&qkv, g_qkv);
    cudaGetSymbolAddress((void**)&att, g_att);
    cudaGetSymbolAddress((void**)&xr, g_xr);
    cudaGetSymbolAddress((void**)&wqkvT, g_wqkvT);
    cudaGetSymbolAddress((void**)&woutT, g_woutT);

    static bool attr_set = false;
    if (!attr_set) {
        cudaFuncSetAttribute(attn_mma_kernel,
                             cudaFuncAttributeMaxDynamicSharedMemorySize, ATT_SMEM);
        cudaFuncSetAttribute(gemm_mma<0>,
                             cudaFuncAttributeMaxDynamicSharedMemorySize, GEMM_SMEM);
        cudaFuncSetAttribute(gemm_mma<1>,
                             cudaFuncAttributeMaxDynamicSharedMemorySize, GEMM_SMEM);
        attr_set = true;
    }

    const int M = Bc * Tc;       // 8192

    // 0) prep: round x; transpose+round weights -> K-major [N, K]
    {
        const int nx = M * Cc;
        round_kernel<<<nx / (256 * 4), 256>>>(x, xr, nx);
        dim3 g1(3 * Cc / 32, Cc / 32);
        transpose_kernel<<<g1, 256>>>(Wqkv, wqkvT, Cc, 3 * Cc);
        dim3 g2(Cc / 32, Cc / 32);
        transpose_kernel<<<g2, 256>>>(Wout, woutT, Cc, Cc);
    }

    // 1) QKV GEMM + bias (tf32 mma.sync) -> g_qkv (V transposed), rounded
    {
        dim3 grid((3 * Cc) / 128, M / 128);   // (24, 64)
        gemm_mma<1><<<grid, 128, GEMM_SMEM>>>(xr, wqkvT, bqkv, nullptr, M, 3 * Cc, Cc);
    }

    // 2) causal flash attention (tf32 mma.sync) -> g_att [B,T,C], rounded
    {
        const float* Qp  = qkv;
        const float* Kp  = qkv + BHTD;
        const float* VTp = qkv + 2 * BHTD;    // [b][h][D][T]
        dim3 grid(Tc / 64, Bc * Hc);          // (32, 64)
        attn_mma_kernel<<<grid, 128, ATT_SMEM>>>(Qp, Kp, VTp, att);
    }

    // 3) output projection + bias (tf32 mma.sync) -> d_out
    {
        dim3 grid(Cc / 128, M / 128);         // (8, 64)
        gemm_mma<0><<<grid, 128, GEMM_SMEM>>>(att, woutT, bout, out, M, Cc, Cc);
    }
}